// round 8
// baseline (speedup 1.0000x reference)
#include <cuda_runtime.h>
#include <cstdint>
#include <cstddef>

#define BB 8
#define SS 2048
#define TT 1024
#define EE 1024
#define HH 16
#define DD 64
#define CC 768

// Scratch (device globals: allocation-free rule)
__device__ float  g_q   [(size_t)BB*HH*SS*DD];   // [B,H,S,D]  64 MB
__device__ float  g_k   [(size_t)BB*HH*DD*TT];   // [B,H,D,T]  32 MB
__device__ float  g_v   [(size_t)BB*HH*TT*DD];   // [B,H,T,D]  32 MB
__device__ float  g_ao  [(size_t)BB*SS*EE];      // attn out [B,S,E] 64 MB
__device__ float  g_praw[(size_t)BB*HH*SS*TT];   // raw scaled scores [B,H,S,T] 1 GiB
__device__ float2 g_stat[(size_t)BB*HH*SS];      // per-row (m, invZ/H) 2 MB

// ---- packed f32x2 helpers ----
__device__ __forceinline__ unsigned long long pack2(float lo, float hi) {
    unsigned long long r;
    asm("mov.b64 %0, {%1, %2};" : "=l"(r) : "f"(lo), "f"(hi));
    return r;
}
__device__ __forceinline__ void unpack2(unsigned long long v, float& lo, float& hi) {
    asm("mov.b64 {%0, %1}, %2;" : "=f"(lo), "=f"(hi) : "l"(v));
}
__device__ __forceinline__ void ffma2(unsigned long long& d, unsigned long long a, unsigned long long b) {
    asm("fma.rn.f32x2 %0, %1, %2, %0;" : "+l"(d) : "l"(a), "l"(b));
}
__device__ __forceinline__ void fmul2(unsigned long long& d, unsigned long long a) {
    asm("mul.rn.f32x2 %0, %0, %1;" : "+l"(d) : "l"(a));
}

// ============================================================================
// GEMM v2: C[M,N] = A[M,K] @ W[K,N] + bias, head-remapped output.
// 128x64 CTA tile, 256 threads, 8(m)x4(n) micro-tile, K-chunk 32.
// A stored DUPLICATED in smem: As2[k][2m]=As2[k][2m+1]=a  -> LDS.64 gives (a,a)
// directly, zero mov.b64 packs in the inner loop. B read as natural f32x2
// pairs via LDS.128.
// mode 0: plain row-major [M,N]
// mode 1: out[((b*H + h)*len + s)*D + d]   (Q, V layouts)
// mode 2: out[((b*H + h)*D + d)*T + s]     (K stored d-major)
// ============================================================================
__global__ __launch_bounds__(256) void gemm_bias_kernel(
    const float* __restrict__ A, const float* __restrict__ W,
    const float* __restrict__ bias, float* __restrict__ Cout,
    int M, int K, int N, int len, int mode)
{
    __shared__ __align__(16) float As2[32][258];  // [k][2m] duplicated, stride even
    __shared__ __align__(16) float Bs [32][68];   // [k][n]

    const int tid = threadIdx.x;
    const int tx = tid & 15;          // n-dim (x4)
    const int ty = tid >> 4;          // m-dim (x8)
    const int tm = blockIdx.y << 7;
    const int tn = blockIdx.x << 6;

    unsigned long long acc[8][2];
#pragma unroll
    for (int i = 0; i < 8; i++) { acc[i][0] = 0ULL; acc[i][1] = 0ULL; }

    for (int k0 = 0; k0 < K; k0 += 32) {
        // Load A tile 128 x 32 (1024 float4), store duplicated-transposed.
#pragma unroll
        for (int i = 0; i < 4; i++) {
            int idx = tid + i * 256;
            int m  = idx >> 3;             // 0..127
            int kb = (idx & 7) << 2;       // 0..28
            float4 av = *(const float4*)(A + (size_t)(tm + m) * K + k0 + kb);
            *(float2*)&As2[kb + 0][m << 1] = make_float2(av.x, av.x);
            *(float2*)&As2[kb + 1][m << 1] = make_float2(av.y, av.y);
            *(float2*)&As2[kb + 2][m << 1] = make_float2(av.z, av.z);
            *(float2*)&As2[kb + 3][m << 1] = make_float2(av.w, av.w);
        }
        // Load B tile 32 x 64 (512 float4)
#pragma unroll
        for (int i = 0; i < 2; i++) {
            int idx = tid + i * 256;
            int kb = idx >> 4;             // 0..31
            int nf = (idx & 15) << 2;      // 0..60
            *(float4*)&Bs[kb][nf] = *(const float4*)(W + (size_t)(k0 + kb) * N + tn + nf);
        }
        __syncthreads();
#pragma unroll
        for (int kk = 0; kk < 32; kk++) {
            ulonglong2 bb = *(const ulonglong2*)&Bs[kk][tx << 2];
#pragma unroll
            for (int i = 0; i < 8; i++) {
                unsigned long long a =
                    *(const unsigned long long*)&As2[kk][((ty << 3) + i) << 1];
                ffma2(acc[i][0], a, bb.x);
                ffma2(acc[i][1], a, bb.y);
            }
        }
        __syncthreads();
    }

#pragma unroll
    for (int i = 0; i < 8; i++) {
        int row = tm + (ty << 3) + i;
#pragma unroll
        for (int j2 = 0; j2 < 2; j2++) {
            float v0, v1;
            unpack2(acc[i][j2], v0, v1);
            int col = tn + (tx << 2) + (j2 << 1);
            v0 += bias[col];
            v1 += bias[col + 1];
            if (mode == 0) {
                Cout[(size_t)row * N + col]     = v0;
                Cout[(size_t)row * N + col + 1] = v1;
            } else {
                int b_ = row / len, s_ = row - b_ * len;
                int h0 = col >> 6, d0 = col & 63;   // col even -> col,col+1 same head
                if (mode == 1) {
                    float* p = Cout + (((size_t)b_ * HH + h0) * len + s_) * DD + d0;
                    p[0] = v0; p[1] = v1;
                } else {
                    float* p = Cout + (((size_t)b_ * HH + h0) * DD + d0) * TT + s_;
                    p[0] = v0; p[TT] = v1;
                }
            }
        }
    }
}

// ============================================================================
// Flash-style attention: one CTA per (b, h, 64-row s-tile). Streams T in
// 64-chunks with online softmax; scores live in registers. Raw scaled scores
// are written to g_praw and per-row (m, invZ/H) to g_stat for the avg kernel.
// smem = 102.9 KB -> 2 CTAs/SM (16 warps).
//
// Layout (floats):
//   sQ2 [64][130]  Q duplicated-transposed: sQ2[d][2s]=(q,q)      8320
//   sK  [64][68]   K chunk, d-major rows                          4352
//   sV  [64][68]   V chunk, t-major rows                          4352
//   sP2 [64][136]  P duplicated: sP2[s][2t]=(p,p)                 8704
// ============================================================================
#define AT_SMEM_FLOATS (8320 + 4352 + 4352 + 8704)
#define AT_SMEM_BYTES  (AT_SMEM_FLOATS * 4)

__global__ __launch_bounds__(256, 2) void attn_flash_kernel(
    const float* __restrict__ q, const float* __restrict__ kdt,
    const float* __restrict__ v, float* __restrict__ ao,
    float* __restrict__ praw, float2* __restrict__ stat)
{
    extern __shared__ __align__(16) float sm[];
    float* sQ2 = sm;
    float* sK  = sm + 8320;
    float* sV  = sm + 12672;
    float* sP2 = sm + 17024;

    const int tid = threadIdx.x;
    const int tx = tid & 15;    // t (phase1) / d (phase3) dim, x4
    const int ty = tid >> 4;    // s dim, x4

    const int bh = blockIdx.x >> 5;              // SS/64 = 32 tiles per head
    const int st = (blockIdx.x & 31) << 6;
    const int b_ = bh >> 4;
    const int h_ = bh & 15;

    const float* qbase = q   + ((size_t)bh * SS + st) * DD;
    const float* kbase = kdt + (size_t)bh * DD * TT;
    const float* vbase = v   + (size_t)bh * TT * DD;

    // Load Q tile [64,64] duplicated-transposed: sQ2[d][2s] = (q,q)
#pragma unroll
    for (int i = 0; i < 4; i++) {
        int idx = tid + i * 256;
        int s_  = idx >> 4;
        int d4  = (idx & 15) << 2;
        float4 qv = *(const float4*)(qbase + (size_t)s_ * DD + d4);
        *(float2*)&sQ2[(d4 + 0) * 130 + (s_ << 1)] = make_float2(qv.x, qv.x);
        *(float2*)&sQ2[(d4 + 1) * 130 + (s_ << 1)] = make_float2(qv.y, qv.y);
        *(float2*)&sQ2[(d4 + 2) * 130 + (s_ << 1)] = make_float2(qv.z, qv.z);
        *(float2*)&sQ2[(d4 + 3) * 130 + (s_ << 1)] = make_float2(qv.w, qv.w);
    }

    unsigned long long oacc[4][2];
    float mrun[4], zrun[4];
#pragma unroll
    for (int i = 0; i < 4; i++) {
        oacc[i][0] = 0ULL; oacc[i][1] = 0ULL;
        mrun[i] = -1e30f;  zrun[i] = 0.f;
    }

    for (int c = 0; c < TT / 64; c++) {
        __syncthreads();   // prev-chunk PV reads of sK/sV done; (iter0: before K/V fill)
        // Load K chunk (d-major) and V chunk (t-major)
#pragma unroll
        for (int i = 0; i < 4; i++) {
            int idx = tid + i * 256;
            int r  = idx >> 4;
            int c4 = (idx & 15) << 2;
            *(float4*)&sK[r * 68 + c4] = *(const float4*)(kbase + (size_t)r * TT + c * 64 + c4);
            *(float4*)&sV[r * 68 + c4] = *(const float4*)(vbase + (size_t)(c * 64 + r) * DD + c4);
        }
        __syncthreads();

        // ---- QK^T chunk: S[64s x 64t], k-depth = 64 d ----
        unsigned long long sacc[4][2] = {{0ULL,0ULL},{0ULL,0ULL},{0ULL,0ULL},{0ULL,0ULL}};
#pragma unroll 16
        for (int kk = 0; kk < 64; kk++) {
            ulonglong2 bb = *(const ulonglong2*)&sK[kk * 68 + (tx << 2)];
#pragma unroll
            for (int i = 0; i < 4; i++) {
                unsigned long long a =
                    *(const unsigned long long*)&sQ2[kk * 130 + (((ty << 2) + i) << 1)];
                ffma2(sacc[i][0], a, bb.x);
                ffma2(sacc[i][1], a, bb.y);
            }
        }

        // ---- online softmax update + raw-score spill + P into smem ----
#pragma unroll
        for (int i = 0; i < 4; i++) {
            float v0, v1, v2, v3;
            unpack2(sacc[i][0], v0, v1);
            unpack2(sacc[i][1], v2, v3);
            v0 *= 0.125f; v1 *= 0.125f; v2 *= 0.125f; v3 *= 0.125f;   // 1/sqrt(64)

            int srow = st + (ty << 2) + i;
            *(float4*)&praw[((size_t)bh * SS + srow) * TT + c * 64 + (tx << 2)] =
                make_float4(v0, v1, v2, v3);

            float cm = fmaxf(fmaxf(v0, v1), fmaxf(v2, v3));
#pragma unroll
            for (int off = 8; off; off >>= 1)
                cm = fmaxf(cm, __shfl_xor_sync(0xffffffffu, cm, off));
            float mn   = fmaxf(mrun[i], cm);
            float corr = __expf(mrun[i] - mn);
            mrun[i] = mn;

            float p0 = __expf(v0 - mn), p1 = __expf(v1 - mn);
            float p2 = __expf(v2 - mn), p3 = __expf(v3 - mn);
            float zs = (p0 + p1) + (p2 + p3);
#pragma unroll
            for (int off = 8; off; off >>= 1)
                zs += __shfl_xor_sync(0xffffffffu, zs, off);
            zrun[i] = zrun[i] * corr + zs;

            unsigned long long cc = pack2(corr, corr);
            fmul2(oacc[i][0], cc);
            fmul2(oacc[i][1], cc);

            float* pp = &sP2[(size_t)((ty << 2) + i) * 136 + (tx << 3)];
            *(float4*)pp       = make_float4(p0, p0, p1, p1);
            *(float4*)(pp + 4) = make_float4(p2, p2, p3, p3);
        }
        __syncwarp();   // sP2 rows are produced & consumed within one half-warp

        // ---- PV chunk: out += P[64s x 64t] @ V[64t x 64d] ----
#pragma unroll 16
        for (int kk = 0; kk < 64; kk++) {
            ulonglong2 vv = *(const ulonglong2*)&sV[kk * 68 + (tx << 2)];
#pragma unroll
            for (int i = 0; i < 4; i++) {
                unsigned long long a =
                    *(const unsigned long long*)&sP2[(size_t)((ty << 2) + i) * 136 + (kk << 1)];
                ffma2(oacc[i][0], a, vv.x);
                ffma2(oacc[i][1], a, vv.y);
            }
        }
    }

    // ---- epilogue: normalize, write out head-slice + per-row stats ----
#pragma unroll
    for (int i = 0; i < 4; i++) {
        float inv = 1.0f / zrun[i];
        float v0, v1, v2, v3;
        unpack2(oacc[i][0], v0, v1);
        unpack2(oacc[i][1], v2, v3);
        int srow = st + (ty << 2) + i;
        float* p = ao + ((size_t)b_ * SS + srow) * EE + h_ * DD + (tx << 2);
        *(float4*)p = make_float4(v0 * inv, v1 * inv, v2 * inv, v3 * inv);
        if (tx == 0)
            stat[(size_t)bh * SS + srow] = make_float2(mrun[i], inv * (1.0f / (float)HH));
    }
}

// ============================================================================
// avg_attn: avg[b,s,t] = (1/H) sum_h exp(praw[b,h,s,t] - m[bh,s]) * invZ[bh,s]
// Pure memory-bound pass over 1.07 GB; no atomics.
// ============================================================================
__global__ __launch_bounds__(256) void avg_kernel(
    const float* __restrict__ praw, const float2* __restrict__ stat,
    float* __restrict__ avg)
{
    size_t gi = (size_t)blockIdx.x * 256 + threadIdx.x;    // over B*S*(T/4)
    int    t4 = (int)(gi & (TT / 4 - 1)) << 2;
    size_t bs = gi >> 8;                                    // / (T/4)
    int b_ = (int)(bs >> 11);                               // / SS
    int s_ = (int)(bs & (SS - 1));

    float a0 = 0.f, a1 = 0.f, a2 = 0.f, a3 = 0.f;
#pragma unroll
    for (int h = 0; h < HH; h++) {
        size_t row = ((size_t)(b_ * HH + h) * SS + s_);
        float2 mz = stat[row];
        float4 r  = *(const float4*)&praw[row * TT + t4];
        a0 += __expf(r.x - mz.x) * mz.y;
        a1 += __expf(r.y - mz.x) * mz.y;
        a2 += __expf(r.z - mz.x) * mz.y;
        a3 += __expf(r.w - mz.x) * mz.y;
    }
    *(float4*)&avg[bs * TT + t4] = make_float4(a0, a1, a2, a3);
}

// ============================================================================
// Launch
// ============================================================================
extern "C" void kernel_launch(void* const* d_in, const int* in_sizes, int n_in,
                              void* d_out, int out_size)
{
    const float* x   = (const float*)d_in[0];
    const float* enc = (const float*)d_in[1];
    const float* Wq  = (const float*)d_in[2];
    const float* bq  = (const float*)d_in[3];
    const float* Wk  = (const float*)d_in[4];
    const float* bk  = (const float*)d_in[5];
    const float* Wv  = (const float*)d_in[6];
    const float* bv  = (const float*)d_in[7];
    const float* Wo  = (const float*)d_in[8];
    const float* bo  = (const float*)d_in[9];

    float* out = (float*)d_out;                       // [B,S,E]
    float* avg = out + (size_t)BB * SS * EE;          // [B,S,T]

    float *qp, *kp, *vp, *aop, *prp;
    float2* stp;
    cudaGetSymbolAddress((void**)&qp,  g_q);
    cudaGetSymbolAddress((void**)&kp,  g_k);
    cudaGetSymbolAddress((void**)&vp,  g_v);
    cudaGetSymbolAddress((void**)&aop, g_ao);
    cudaGetSymbolAddress((void**)&prp, g_praw);
    cudaGetSymbolAddress((void**)&stp, g_stat);

    cudaFuncSetAttribute(attn_flash_kernel,
                         cudaFuncAttributeMaxDynamicSharedMemorySize, AT_SMEM_BYTES);

    // Q = x @ Wq + bq        -> [B,H,S,D]
    gemm_bias_kernel<<<dim3(EE / 64, (BB * SS) / 128), 256>>>(x,   Wq, bq, qp,  BB * SS, EE, EE, SS, 1);
    // K = enc @ Wk + bk      -> [B,H,D,T] (d-major)
    gemm_bias_kernel<<<dim3(EE / 64, (BB * TT) / 128), 256>>>(enc, Wk, bk, kp,  BB * TT, CC, EE, TT, 2);
    // V = enc @ Wv + bv      -> [B,H,T,D]
    gemm_bias_kernel<<<dim3(EE / 64, (BB * TT) / 128), 256>>>(enc, Wv, bv, vp,  BB * TT, CC, EE, TT, 1);
    // flash attention (writes g_ao, g_praw, g_stat)
    attn_flash_kernel<<<BB * HH * (SS / 64), 256, AT_SMEM_BYTES>>>(qp, kp, vp, aop, prp, stp);
    // avg_attn from raw scores + stats
    avg_kernel<<<(unsigned)((size_t)BB * SS * (TT / 4) / 256), 256>>>(prp, stp, avg);
    // out = attn_out @ Wo + bo
    gemm_bias_kernel<<<dim3(EE / 64, (BB * SS) / 128), 256>>>(aop, Wo, bo, out, BB * SS, EE, EE, 0, 0);
}

// round 10
// speedup vs baseline: 1.3896x; 1.3896x over previous
#include <cuda_runtime.h>
#include <cuda_bf16.h>
#include <cstdint>
#include <cstddef>

#define BB 8
#define SS 2048
#define TT 1024
#define EE 1024
#define HH 16
#define DD 64
#define CC 768

// ---------------- scratch (device globals: allocation-free rule) ----------------
__device__ float  g_q   [(size_t)BB*HH*SS*DD];   // [B,H,S,D]  64 MB
__device__ float  g_k   [(size_t)BB*HH*DD*TT];   // [B,H,D,T]  32 MB
__device__ float  g_v   [(size_t)BB*HH*TT*DD];   // [B,H,T,D]  32 MB
__device__ float  g_ao  [(size_t)BB*SS*EE];      // attn out [B,S,E] 64 MB
__device__ float  g_praw[(size_t)BB*HH*SS*TT];   // raw scaled scores 1 GiB
__device__ float2 g_stat[(size_t)BB*HH*SS];      // per-row (m, invZ/H)

// bf16 split operands
__device__ __nv_bfloat16 g_xh [(size_t)BB*SS*EE], g_xl [(size_t)BB*SS*EE];
__device__ __nv_bfloat16 g_eh [(size_t)BB*TT*CC], g_el [(size_t)BB*TT*CC];
__device__ __nv_bfloat16 g_aoh[(size_t)BB*SS*EE], g_aol[(size_t)BB*SS*EE];
__device__ __nv_bfloat16 g_wqh[(size_t)EE*EE], g_wql[(size_t)EE*EE];   // [N,K] transposed
__device__ __nv_bfloat16 g_wkh[(size_t)EE*CC], g_wkl[(size_t)EE*CC];
__device__ __nv_bfloat16 g_wvh[(size_t)EE*CC], g_wvl[(size_t)EE*CC];
__device__ __nv_bfloat16 g_woh[(size_t)EE*EE], g_wol[(size_t)EE*EE];

// ---------------- warp-level MMA helpers (baseline PTX, no arch-variant gates) ----
__device__ __forceinline__ uint32_t smem_to_u32(const void* p) {
    uint32_t a;
    asm("{ .reg .u64 t; cvta.to.shared.u64 t, %1; cvt.u32.u64 %0, t; }" : "=r"(a) : "l"(p));
    return a;
}
__device__ __forceinline__ void ldm_x4(uint32_t* r, uint32_t addr) {
    asm volatile("ldmatrix.sync.aligned.m8n8.x4.shared.b16 {%0,%1,%2,%3}, [%4];"
                 : "=r"(r[0]), "=r"(r[1]), "=r"(r[2]), "=r"(r[3]) : "r"(addr));
}
__device__ __forceinline__ void mma_bf16(float* d, const uint32_t* a, const uint32_t* b) {
    asm volatile(
        "mma.sync.aligned.m16n8k16.row.col.f32.bf16.bf16.f32 "
        "{%0,%1,%2,%3}, {%4,%5,%6,%7}, {%8,%9}, {%0,%1,%2,%3};"
        : "+f"(d[0]), "+f"(d[1]), "+f"(d[2]), "+f"(d[3])
        : "r"(a[0]), "r"(a[1]), "r"(a[2]), "r"(a[3]), "r"(b[0]), "r"(b[1]));
}

// ---- packed f32x2 helpers (attention kernel) ----
__device__ __forceinline__ unsigned long long pack2(float lo, float hi) {
    unsigned long long r;
    asm("mov.b64 %0, {%1, %2};" : "=l"(r) : "f"(lo), "f"(hi));
    return r;
}
__device__ __forceinline__ void unpack2(unsigned long long v, float& lo, float& hi) {
    asm("mov.b64 {%0, %1}, %2;" : "=f"(lo), "=f"(hi) : "l"(v));
}
__device__ __forceinline__ void ffma2(unsigned long long& d, unsigned long long a, unsigned long long b) {
    asm("fma.rn.f32x2 %0, %1, %2, %0;" : "+l"(d) : "l"(a), "l"(b));
}
__device__ __forceinline__ void fmul2(unsigned long long& d, unsigned long long a) {
    asm("mul.rn.f32x2 %0, %0, %1;" : "+l"(d) : "l"(a));
}

// ============================================================================
// split: fp32 -> (bf16 hi, bf16 lo) elementwise, float4-vectorized
// ============================================================================
__global__ __launch_bounds__(256) void split_kernel(
    const float4* __restrict__ src, uint2* __restrict__ hi, uint2* __restrict__ lo, int n4)
{
    int i = blockIdx.x * 256 + threadIdx.x;
    if (i >= n4) return;
    float4 v = src[i];
    __nv_bfloat16 hx = __float2bfloat16(v.x), hy = __float2bfloat16(v.y);
    __nv_bfloat16 hz = __float2bfloat16(v.z), hw = __float2bfloat16(v.w);
    __nv_bfloat16 lx = __float2bfloat16(v.x - __bfloat162float(hx));
    __nv_bfloat16 ly = __float2bfloat16(v.y - __bfloat162float(hy));
    __nv_bfloat16 lz = __float2bfloat16(v.z - __bfloat162float(hz));
    __nv_bfloat16 lw = __float2bfloat16(v.w - __bfloat162float(hw));
    uint2 H, L;
    H.x = (uint32_t)__bfloat16_as_ushort(hx) | ((uint32_t)__bfloat16_as_ushort(hy) << 16);
    H.y = (uint32_t)__bfloat16_as_ushort(hz) | ((uint32_t)__bfloat16_as_ushort(hw) << 16);
    L.x = (uint32_t)__bfloat16_as_ushort(lx) | ((uint32_t)__bfloat16_as_ushort(ly) << 16);
    L.y = (uint32_t)__bfloat16_as_ushort(lz) | ((uint32_t)__bfloat16_as_ushort(lw) << 16);
    hi[i] = H; lo[i] = L;
}

// ============================================================================
// weight transpose+split: W[K,N] -> th/tl [N,K] (B-operand layout), smem-tiled
// ============================================================================
__global__ void wsplit_kernel(const float* __restrict__ W,
                              __nv_bfloat16* __restrict__ th, __nv_bfloat16* __restrict__ tl,
                              int K, int N)
{
    __shared__ float t[32][33];
    int n0 = blockIdx.x << 5, k0 = blockIdx.y << 5;
    int tx = threadIdx.x, ty = threadIdx.y;        // block (32, 8)
#pragma unroll
    for (int r = ty; r < 32; r += 8)
        t[r][tx] = W[(size_t)(k0 + r) * N + n0 + tx];
    __syncthreads();
#pragma unroll
    for (int r = ty; r < 32; r += 8) {
        float v = t[tx][r];                         // = W[k0+tx][n0+r]
        __nv_bfloat16 h = __float2bfloat16(v);
        __nv_bfloat16 l = __float2bfloat16(v - __bfloat162float(h));
        th[(size_t)(n0 + r) * K + k0 + tx] = h;
        tl[(size_t)(n0 + r) * K + k0 + tx] = l;
    }
}

// ============================================================================
// HMMA GEMM: C[128m x 128n] per CTA, 512 threads (16 warps, 4x4), warp 32x32.
// 2-term bf16 split: D = Ah*Bh + Ah*Bl + Al*Bh, fp32 accumulate.
// A = [M,K] hi/lo bf16; B = [N,K] hi/lo bf16 (pre-transposed weights).
// smem stride 40 bf16 (80B) -> ldmatrix 8-row reads conflict-free.
// mode 0: C[m, col]; mode 1: out[((b*H+h)*len+s)*D + d]; mode 2: out[((b*H+h)*D+d)*len + s]
// ============================================================================
#define GST 40   // smem row stride in bf16 elements

__global__ __launch_bounds__(512) void gemm_mma_kernel(
    const __nv_bfloat16* __restrict__ Ah, const __nv_bfloat16* __restrict__ Al,
    const __nv_bfloat16* __restrict__ Bh, const __nv_bfloat16* __restrict__ Bl,
    const float* __restrict__ bias, float* __restrict__ Cout,
    int K, int len, int mode)
{
    __shared__ __align__(16) __nv_bfloat16 sAh[128 * GST], sAl[128 * GST];
    __shared__ __align__(16) __nv_bfloat16 sBh[128 * GST], sBl[128 * GST];

    const int tid  = threadIdx.x;
    const int wid  = tid >> 5;
    const int lane = tid & 31;
    const int tm = blockIdx.y << 7;
    const int tn = blockIdx.x << 7;

    const int wm = (wid >> 2) << 5;      // warp m offset (0..96)
    const int wn = (wid & 3) << 5;       // warp n offset (0..96)

    const uint32_t uAh = smem_to_u32(sAh), uAl = smem_to_u32(sAl);
    const uint32_t uBh = smem_to_u32(sBh), uBl = smem_to_u32(sBl);

    // fill addressing: 512 threads, 128 rows x 32k per tile -> 1 uint4/thread/tile
    const int fr = tid >> 2;             // 0..127
    const int fk = (tid & 3) << 3;       // 0,8,16,24
    const uint32_t fso = (uint32_t)(fr * GST + fk) * 2;

    // ldmatrix lane addressing (element offsets within chunk)
    const int a_row = lane & 15;
    const int a_kof = (lane >> 4) << 3;                 // 0 or 8
    const int b_row = (lane & 7) + ((lane & 16) ? 8 : 0);
    const int b_kof = (lane & 8) ? 8 : 0;

    float d[2][4][4];
#pragma unroll
    for (int i = 0; i < 2; i++)
#pragma unroll
        for (int j = 0; j < 4; j++)
#pragma unroll
            for (int q = 0; q < 4; q++) d[i][j][q] = 0.f;

    const int nchunks = K >> 5;
    for (int c = 0; c < nchunks; c++) {
        const int k0 = c << 5;
        size_t goA = (size_t)(tm + fr) * K + k0 + fk;
        size_t goB = (size_t)(tn + fr) * K + k0 + fk;
        uint4 vAh = *(const uint4*)(Ah + goA);
        uint4 vAl = *(const uint4*)(Al + goA);
        uint4 vBh = *(const uint4*)(Bh + goB);
        uint4 vBl = *(const uint4*)(Bl + goB);
        __syncthreads();
        *(uint4*)((char*)sAh + fso) = vAh;
        *(uint4*)((char*)sAl + fso) = vAl;
        *(uint4*)((char*)sBh + fso) = vBh;
        *(uint4*)((char*)sBl + fso) = vBl;
        __syncthreads();

#pragma unroll
        for (int ks = 0; ks < 32; ks += 16) {
            uint32_t ah[2][4], al[2][4], bh[2][4], bl[2][4];
#pragma unroll
            for (int ms = 0; ms < 2; ms++) {
                uint32_t off = (uint32_t)((wm + (ms << 4) + a_row) * GST + ks + a_kof) * 2;
                ldm_x4(ah[ms], uAh + off);
                ldm_x4(al[ms], uAl + off);
            }
#pragma unroll
            for (int g = 0; g < 2; g++) {
                uint32_t off = (uint32_t)((wn + (g << 4) + b_row) * GST + ks + b_kof) * 2;
                ldm_x4(bh[g], uBh + off);
                ldm_x4(bl[g], uBl + off);
            }
#pragma unroll
            for (int ms = 0; ms < 2; ms++)
#pragma unroll
                for (int g = 0; g < 2; g++)
#pragma unroll
                    for (int h = 0; h < 2; h++) {
                        float* dd = d[ms][(g << 1) + h];
                        mma_bf16(dd, ah[ms], &bh[g][h << 1]);
                        mma_bf16(dd, ah[ms], &bl[g][h << 1]);
                        mma_bf16(dd, al[ms], &bh[g][h << 1]);
                    }
        }
    }

    // ---- epilogue ----
    const int qr = lane >> 2;          // 0..7
    const int qc = (lane & 3) << 1;    // 0,2,4,6
#pragma unroll
    for (int ms = 0; ms < 2; ms++) {
#pragma unroll
        for (int half = 0; half < 2; half++) {
            int row = tm + wm + (ms << 4) + (half << 3) + qr;
            int b_ = 0, s_ = row;
            if (mode != 0) { b_ = row / len; s_ = row - b_ * len; }
#pragma unroll
            for (int ng = 0; ng < 4; ng++) {
                int col = tn + wn + (ng << 3) + qc;
                float v0 = d[ms][ng][(half << 1) + 0] + bias[col];
                float v1 = d[ms][ng][(half << 1) + 1] + bias[col + 1];
                if (mode == 0) {
                    *(float2*)&Cout[(size_t)row * EE + col] = make_float2(v0, v1);
                } else if (mode == 1) {
                    int h0 = col >> 6, d0 = col & 63;
                    float* p = Cout + (((size_t)b_ * HH + h0) * len + s_) * DD + d0;
                    *(float2*)p = make_float2(v0, v1);
                } else {
                    int h0 = col >> 6, d0 = col & 63;
                    float* p = Cout + (((size_t)b_ * HH + h0) * DD + d0) * (size_t)len + s_;
                    p[0] = v0; p[len] = v1;
                }
            }
        }
    }
}

// ============================================================================
// Flash-style attention (unchanged winner): fp32 + f32x2.
// ============================================================================
#define AT_SMEM_FLOATS (8320 + 4352 + 4352 + 8704)
#define AT_SMEM_BYTES  (AT_SMEM_FLOATS * 4)

__global__ __launch_bounds__(256, 2) void attn_flash_kernel(
    const float* __restrict__ q, const float* __restrict__ kdt,
    const float* __restrict__ v, float* __restrict__ ao,
    float* __restrict__ praw, float2* __restrict__ stat)
{
    extern __shared__ __align__(16) float sm[];
    float* sQ2 = sm;
    float* sK  = sm + 8320;
    float* sV  = sm + 12672;
    float* sP2 = sm + 17024;

    const int tid = threadIdx.x;
    const int tx = tid & 15;
    const int ty = tid >> 4;

    const int bh = blockIdx.x >> 5;
    const int st = (blockIdx.x & 31) << 6;
    const int b_ = bh >> 4;
    const int h_ = bh & 15;

    const float* qbase = q   + ((size_t)bh * SS + st) * DD;
    const float* kbase = kdt + (size_t)bh * DD * TT;
    const float* vbase = v   + (size_t)bh * TT * DD;

#pragma unroll
    for (int i = 0; i < 4; i++) {
        int idx = tid + i * 256;
        int s_  = idx >> 4;
        int d4  = (idx & 15) << 2;
        float4 qv = *(const float4*)(qbase + (size_t)s_ * DD + d4);
        *(float2*)&sQ2[(d4 + 0) * 130 + (s_ << 1)] = make_float2(qv.x, qv.x);
        *(float2*)&sQ2[(d4 + 1) * 130 + (s_ << 1)] = make_float2(qv.y, qv.y);
        *(float2*)&sQ2[(d4 + 2) * 130 + (s_ << 1)] = make_float2(qv.z, qv.z);
        *(float2*)&sQ2[(d4 + 3) * 130 + (s_ << 1)] = make_float2(qv.w, qv.w);
    }

    unsigned long long oacc[4][2];
    float mrun[4], zrun[4];
#pragma unroll
    for (int i = 0; i < 4; i++) {
        oacc[i][0] = 0ULL; oacc[i][1] = 0ULL;
        mrun[i] = -1e30f;  zrun[i] = 0.f;
    }

    for (int c = 0; c < TT / 64; c++) {
        __syncthreads();
#pragma unroll
        for (int i = 0; i < 4; i++) {
            int idx = tid + i * 256;
            int r  = idx >> 4;
            int c4 = (idx & 15) << 2;
            *(float4*)&sK[r * 68 + c4] = *(const float4*)(kbase + (size_t)r * TT + c * 64 + c4);
            *(float4*)&sV[r * 68 + c4] = *(const float4*)(vbase + (size_t)(c * 64 + r) * DD + c4);
        }
        __syncthreads();

        unsigned long long sacc[4][2] = {{0ULL,0ULL},{0ULL,0ULL},{0ULL,0ULL},{0ULL,0ULL}};
#pragma unroll 16
        for (int kk = 0; kk < 64; kk++) {
            ulonglong2 bb = *(const ulonglong2*)&sK[kk * 68 + (tx << 2)];
#pragma unroll
            for (int i = 0; i < 4; i++) {
                unsigned long long a =
                    *(const unsigned long long*)&sQ2[kk * 130 + (((ty << 2) + i) << 1)];
                ffma2(sacc[i][0], a, bb.x);
                ffma2(sacc[i][1], a, bb.y);
            }
        }

#pragma unroll
        for (int i = 0; i < 4; i++) {
            float v0, v1, v2, v3;
            unpack2(sacc[i][0], v0, v1);
            unpack2(sacc[i][1], v2, v3);
            v0 *= 0.125f; v1 *= 0.125f; v2 *= 0.125f; v3 *= 0.125f;

            int srow = st + (ty << 2) + i;
            *(float4*)&praw[((size_t)bh * SS + srow) * TT + c * 64 + (tx << 2)] =
                make_float4(v0, v1, v2, v3);

            float cm = fmaxf(fmaxf(v0, v1), fmaxf(v2, v3));
#pragma unroll
            for (int off = 8; off; off >>= 1)
                cm = fmaxf(cm, __shfl_xor_sync(0xffffffffu, cm, off));
            float mn   = fmaxf(mrun[i], cm);
            float corr = __expf(mrun[i] - mn);
            mrun[i] = mn;

            float p0 = __expf(v0 - mn), p1 = __expf(v1 - mn);
            float p2 = __expf(v2 - mn), p3 = __expf(v3 - mn);
            float zs = (p0 + p1) + (p2 + p3);
#pragma unroll
            for (int off = 8; off; off >>= 1)
                zs += __shfl_xor_sync(0xffffffffu, zs, off);
            zrun[i] = zrun[i] * corr + zs;

            unsigned long long cc = pack2(corr, corr);
            fmul2(oacc[i][0], cc);
            fmul2(oacc[i][1], cc);

            float* pp = &sP2[(size_t)((ty << 2) + i) * 136 + (tx << 3)];
            *(float4*)pp       = make_float4(p0, p0, p1, p1);
            *(float4*)(pp + 4) = make_float4(p2, p2, p3, p3);
        }
        __syncwarp();

#pragma unroll 16
        for (int kk = 0; kk < 64; kk++) {
            ulonglong2 vv = *(const ulonglong2*)&sV[kk * 68 + (tx << 2)];
#pragma unroll
            for (int i = 0; i < 4; i++) {
                unsigned long long a =
                    *(const unsigned long long*)&sP2[(size_t)((ty << 2) + i) * 136 + (kk << 1)];
                ffma2(oacc[i][0], a, vv.x);
                ffma2(oacc[i][1], a, vv.y);
            }
        }
    }

#pragma unroll
    for (int i = 0; i < 4; i++) {
        float inv = 1.0f / zrun[i];
        float v0, v1, v2, v3;
        unpack2(oacc[i][0], v0, v1);
        unpack2(oacc[i][1], v2, v3);
        int srow = st + (ty << 2) + i;
        float* p = ao + ((size_t)b_ * SS + srow) * EE + h_ * DD + (tx << 2);
        *(float4*)p = make_float4(v0 * inv, v1 * inv, v2 * inv, v3 * inv);
        if (tx == 0)
            stat[(size_t)bh * SS + srow] = make_float2(mrun[i], inv * (1.0f / (float)HH));
    }
}

// ============================================================================
// avg_attn reconstruction (unchanged)
// ============================================================================
__global__ __launch_bounds__(256) void avg_kernel(
    const float* __restrict__ praw, const float2* __restrict__ stat,
    float* __restrict__ avg)
{
    size_t gi = (size_t)blockIdx.x * 256 + threadIdx.x;
    int    t4 = (int)(gi & (TT / 4 - 1)) << 2;
    size_t bs = gi >> 8;
    int b_ = (int)(bs >> 11);
    int s_ = (int)(bs & (SS - 1));

    float a0 = 0.f, a1 = 0.f, a2 = 0.f, a3 = 0.f;
#pragma unroll
    for (int h = 0; h < HH; h++) {
        size_t row = ((size_t)(b_ * HH + h) * SS + s_);
        float2 mz = stat[row];
        float4 r  = *(const float4*)&praw[row * TT + t4];
        a0 += __expf(r.x - mz.x) * mz.y;
        a1 += __expf(r.y - mz.x) * mz.y;
        a2 += __expf(r.z - mz.x) * mz.y;
        a3 += __expf(r.w - mz.x) * mz.y;
    }
    *(float4*)&avg[bs * TT + t4] = make_float4(a0, a1, a2, a3);
}

// ============================================================================
// Launch
// ============================================================================
extern "C" void kernel_launch(void* const* d_in, const int* in_sizes, int n_in,
                              void* d_out, int out_size)
{
    const float* x   = (const float*)d_in[0];
    const float* enc = (const float*)d_in[1];
    const float* Wq  = (const float*)d_in[2];
    const float* bq  = (const float*)d_in[3];
    const float* Wk  = (const float*)d_in[4];
    const float* bk  = (const float*)d_in[5];
    const float* Wv  = (const float*)d_in[6];
    const float* bv  = (const float*)d_in[7];
    const float* Wo  = (const float*)d_in[8];
    const float* bo  = (const float*)d_in[9];

    float* out = (float*)d_out;                       // [B,S,E]
    float* avg = out + (size_t)BB * SS * EE;          // [B,S,T]

    float *qp, *kp, *vp, *aop, *prp;
    float2* stp;
    cudaGetSymbolAddress((void**)&qp,  g_q);
    cudaGetSymbolAddress((void**)&kp,  g_k);
    cudaGetSymbolAddress((void**)&vp,  g_v);
    cudaGetSymbolAddress((void**)&aop, g_ao);
    cudaGetSymbolAddress((void**)&prp, g_praw);
    cudaGetSymbolAddress((void**)&stp, g_stat);

    __nv_bfloat16 *xh, *xl, *eh, *el, *aoh, *aol;
    __nv_bfloat16 *wqh, *wql, *wkh, *wkl, *wvh, *wvl, *woh, *wol;
    cudaGetSymbolAddress((void**)&xh,  g_xh);  cudaGetSymbolAddress((void**)&xl,  g_xl);
    cudaGetSymbolAddress((void**)&eh,  g_eh);  cudaGetSymbolAddress((void**)&el,  g_el);
    cudaGetSymbolAddress((void**)&aoh, g_aoh); cudaGetSymbolAddress((void**)&aol, g_aol);
    cudaGetSymbolAddress((void**)&wqh, g_wqh); cudaGetSymbolAddress((void**)&wql, g_wql);
    cudaGetSymbolAddress((void**)&wkh, g_wkh); cudaGetSymbolAddress((void**)&wkl, g_wkl);
    cudaGetSymbolAddress((void**)&wvh, g_wvh); cudaGetSymbolAddress((void**)&wvl, g_wvl);
    cudaGetSymbolAddress((void**)&woh, g_woh); cudaGetSymbolAddress((void**)&wol, g_wol);

    cudaFuncSetAttribute(attn_flash_kernel,
                         cudaFuncAttributeMaxDynamicSharedMemorySize, AT_SMEM_BYTES);

    // ---- split inputs to bf16 hi/lo ----
    const int n4x = BB * SS * EE / 4;     // 4.19M
    const int n4e = BB * TT * CC / 4;     // 1.57M
    split_kernel<<<n4x / 256, 256>>>((const float4*)x,   (uint2*)xh, (uint2*)xl, n4x);
    split_kernel<<<n4e / 256, 256>>>((const float4*)enc, (uint2*)eh, (uint2*)el, n4e);
    wsplit_kernel<<<dim3(EE / 32, EE / 32), dim3(32, 8)>>>(Wq, wqh, wql, EE, EE);
    wsplit_kernel<<<dim3(EE / 32, CC / 32), dim3(32, 8)>>>(Wk, wkh, wkl, CC, EE);
    wsplit_kernel<<<dim3(EE / 32, CC / 32), dim3(32, 8)>>>(Wv, wvh, wvl, CC, EE);
    wsplit_kernel<<<dim3(EE / 32, EE / 32), dim3(32, 8)>>>(Wo, woh, wol, EE, EE);

    // ---- projections on tensor cores (warp-level HMMA) ----
    gemm_mma_kernel<<<dim3(EE / 128, BB * SS / 128), 512>>>(
        xh, xl, wqh, wql, bq, qp, EE, SS, 1);
    gemm_mma_kernel<<<dim3(EE / 128, BB * TT / 128), 512>>>(
        eh, el, wkh, wkl, bk, kp, CC, TT, 2);
    gemm_mma_kernel<<<dim3(EE / 128, BB * TT / 128), 512>>>(
        eh, el, wvh, wvl, bv, vp, CC, TT, 1);

    // ---- attention (fp32 flash) ----
    attn_flash_kernel<<<BB * HH * (SS / 64), 256, AT_SMEM_BYTES>>>(qp, kp, vp, aop, prp, stp);

    // ---- output projection ----
    split_kernel<<<n4x / 256, 256>>>((const float4*)aop, (uint2*)aoh, (uint2*)aol, n4x);
    gemm_mma_kernel<<<dim3(EE / 128, BB * SS / 128), 512>>>(
        aoh, aol, woh, wol, bo, out, EE, 0, 0);

    // ---- avg_attn ----
    avg_kernel<<<(unsigned)((size_t)BB * SS * (TT / 4) / 256), 256>>>(prp, stp, avg);
}

// round 11
// speedup vs baseline: 1.5316x; 1.1022x over previous
#include <cuda_runtime.h>
#include <cuda_bf16.h>
#include <cstdint>
#include <cstddef>

#define BB 8
#define SS 2048
#define TT 1024
#define EE 1024
#define HH 16
#define DD 64
#define CC 768

// ---------------- scratch (device globals: allocation-free rule) ----------------
__device__ float  g_ao  [(size_t)BB*SS*EE];      // attn out [B,S,E] 64 MB
__device__ float  g_praw[(size_t)BB*HH*SS*TT];   // raw scaled scores 1 GiB
__device__ float2 g_stat[(size_t)BB*HH*SS];      // per-row (m, invZ/H)

// bf16 split operands
__device__ __nv_bfloat16 g_xh [(size_t)BB*SS*EE], g_xl [(size_t)BB*SS*EE];
__device__ __nv_bfloat16 g_eh [(size_t)BB*TT*CC], g_el [(size_t)BB*TT*CC];
__device__ __nv_bfloat16 g_aoh[(size_t)BB*SS*EE], g_aol[(size_t)BB*SS*EE];
__device__ __nv_bfloat16 g_wqh[(size_t)EE*EE], g_wql[(size_t)EE*EE];   // [N,K] transposed
__device__ __nv_bfloat16 g_wkh[(size_t)EE*CC], g_wkl[(size_t)EE*CC];
__device__ __nv_bfloat16 g_wvh[(size_t)EE*CC], g_wvl[(size_t)EE*CC];
__device__ __nv_bfloat16 g_woh[(size_t)EE*EE], g_wol[(size_t)EE*EE];
// bf16 split Q/K/V (written by projection GEMM epilogues)
__device__ __nv_bfloat16 g_qbh[(size_t)BB*HH*SS*DD], g_qbl[(size_t)BB*HH*SS*DD]; // [B,H,S,D], pre-scaled 1/8
__device__ __nv_bfloat16 g_kbh[(size_t)BB*HH*TT*DD], g_kbl[(size_t)BB*HH*TT*DD]; // [B,H,T,D]
__device__ __nv_bfloat16 g_vbh[(size_t)BB*HH*DD*TT], g_vbl[(size_t)BB*HH*DD*TT]; // [B,H,D,T] d-major

// ---------------- warp-level MMA helpers (baseline PTX, no arch-variant gates) ----
__device__ __forceinline__ uint32_t smem_to_u32(const void* p) {
    uint32_t a;
    asm("{ .reg .u64 t; cvta.to.shared.u64 t, %1; cvt.u32.u64 %0, t; }" : "=r"(a) : "l"(p));
    return a;
}
__device__ __forceinline__ void ldm_x4(uint32_t* r, uint32_t addr) {
    asm volatile("ldmatrix.sync.aligned.m8n8.x4.shared.b16 {%0,%1,%2,%3}, [%4];"
                 : "=r"(r[0]), "=r"(r[1]), "=r"(r[2]), "=r"(r[3]) : "r"(addr));
}
__device__ __forceinline__ void mma_bf16(float* d, const uint32_t* a, const uint32_t* b) {
    asm volatile(
        "mma.sync.aligned.m16n8k16.row.col.f32.bf16.bf16.f32 "
        "{%0,%1,%2,%3}, {%4,%5,%6,%7}, {%8,%9}, {%0,%1,%2,%3};"
        : "+f"(d[0]), "+f"(d[1]), "+f"(d[2]), "+f"(d[3])
        : "r"(a[0]), "r"(a[1]), "r"(a[2]), "r"(a[3]), "r"(b[0]), "r"(b[1]));
}
__device__ __forceinline__ uint32_t bf16x2_hi(float a, float b) {  // lo=a, hi=b
    return (uint32_t)__bfloat16_as_ushort(__float2bfloat16(a)) |
           ((uint32_t)__bfloat16_as_ushort(__float2bfloat16(b)) << 16);
}

// ============================================================================
// split: fp32 -> (bf16 hi, bf16 lo) elementwise, float4-vectorized
// ============================================================================
__global__ __launch_bounds__(256) void split_kernel(
    const float4* __restrict__ src, uint2* __restrict__ hi, uint2* __restrict__ lo, int n4)
{
    int i = blockIdx.x * 256 + threadIdx.x;
    if (i >= n4) return;
    float4 v = src[i];
    __nv_bfloat16 hx = __float2bfloat16(v.x), hy = __float2bfloat16(v.y);
    __nv_bfloat16 hz = __float2bfloat16(v.z), hw = __float2bfloat16(v.w);
    __nv_bfloat16 lx = __float2bfloat16(v.x - __bfloat162float(hx));
    __nv_bfloat16 ly = __float2bfloat16(v.y - __bfloat162float(hy));
    __nv_bfloat16 lz = __float2bfloat16(v.z - __bfloat162float(hz));
    __nv_bfloat16 lw = __float2bfloat16(v.w - __bfloat162float(hw));
    uint2 H, L;
    H.x = (uint32_t)__bfloat16_as_ushort(hx) | ((uint32_t)__bfloat16_as_ushort(hy) << 16);
    H.y = (uint32_t)__bfloat16_as_ushort(hz) | ((uint32_t)__bfloat16_as_ushort(hw) << 16);
    L.x = (uint32_t)__bfloat16_as_ushort(lx) | ((uint32_t)__bfloat16_as_ushort(ly) << 16);
    L.y = (uint32_t)__bfloat16_as_ushort(lz) | ((uint32_t)__bfloat16_as_ushort(lw) << 16);
    hi[i] = H; lo[i] = L;
}

// ============================================================================
// weight transpose+split: W[K,N] -> th/tl [N,K] (B-operand layout), smem-tiled
// ============================================================================
__global__ void wsplit_kernel(const float* __restrict__ W,
                              __nv_bfloat16* __restrict__ th, __nv_bfloat16* __restrict__ tl,
                              int K, int N)
{
    __shared__ float t[32][33];
    int n0 = blockIdx.x << 5, k0 = blockIdx.y << 5;
    int tx = threadIdx.x, ty = threadIdx.y;        // block (32, 8)
#pragma unroll
    for (int r = ty; r < 32; r += 8)
        t[r][tx] = W[(size_t)(k0 + r) * N + n0 + tx];
    __syncthreads();
#pragma unroll
    for (int r = ty; r < 32; r += 8) {
        float v = t[tx][r];
        __nv_bfloat16 h = __float2bfloat16(v);
        __nv_bfloat16 l = __float2bfloat16(v - __bfloat162float(h));
        th[(size_t)(n0 + r) * K + k0 + tx] = h;
        tl[(size_t)(n0 + r) * K + k0 + tx] = l;
    }
}

// ============================================================================
// HMMA GEMM (R10 core): C[128 x 128], 512 threads, warp 32x32, bf16 2-term split.
// Epilogue modes:
//   0: fp32 C[m, col] row-major (writes d_out)
//   3: bf16 hi/lo out[((b*H+h)*len+s)*D + d], value scaled by `scale`
//   4: bf16 hi/lo out[((b*H+h)*D+d)*len + s]
// ============================================================================
#define GST 40

__global__ __launch_bounds__(512) void gemm_mma_kernel(
    const __nv_bfloat16* __restrict__ Ah, const __nv_bfloat16* __restrict__ Al,
    const __nv_bfloat16* __restrict__ Bh, const __nv_bfloat16* __restrict__ Bl,
    const float* __restrict__ bias, float* __restrict__ Cout,
    __nv_bfloat16* __restrict__ Outh, __nv_bfloat16* __restrict__ Outl,
    float scale, int K, int len, int mode)
{
    __shared__ __align__(16) __nv_bfloat16 sAh[128 * GST], sAl[128 * GST];
    __shared__ __align__(16) __nv_bfloat16 sBh[128 * GST], sBl[128 * GST];

    const int tid  = threadIdx.x;
    const int wid  = tid >> 5;
    const int lane = tid & 31;
    const int tm = blockIdx.y << 7;
    const int tn = blockIdx.x << 7;

    const int wm = (wid >> 2) << 5;
    const int wn = (wid & 3) << 5;

    const uint32_t uAh = smem_to_u32(sAh), uAl = smem_to_u32(sAl);
    const uint32_t uBh = smem_to_u32(sBh), uBl = smem_to_u32(sBl);

    const int fr = tid >> 2;
    const int fk = (tid & 3) << 3;
    const uint32_t fso = (uint32_t)(fr * GST + fk) * 2;

    const int a_row = lane & 15;
    const int a_kof = (lane >> 4) << 3;
    const int b_row = (lane & 7) + ((lane & 16) ? 8 : 0);
    const int b_kof = (lane & 8) ? 8 : 0;

    float d[2][4][4];
#pragma unroll
    for (int i = 0; i < 2; i++)
#pragma unroll
        for (int j = 0; j < 4; j++)
#pragma unroll
            for (int q = 0; q < 4; q++) d[i][j][q] = 0.f;

    const int nchunks = K >> 5;
    for (int c = 0; c < nchunks; c++) {
        const int k0 = c << 5;
        size_t goA = (size_t)(tm + fr) * K + k0 + fk;
        size_t goB = (size_t)(tn + fr) * K + k0 + fk;
        uint4 vAh = *(const uint4*)(Ah + goA);
        uint4 vAl = *(const uint4*)(Al + goA);
        uint4 vBh = *(const uint4*)(Bh + goB);
        uint4 vBl = *(const uint4*)(Bl + goB);
        __syncthreads();
        *(uint4*)((char*)sAh + fso) = vAh;
        *(uint4*)((char*)sAl + fso) = vAl;
        *(uint4*)((char*)sBh + fso) = vBh;
        *(uint4*)((char*)sBl + fso) = vBl;
        __syncthreads();

#pragma unroll
        for (int ks = 0; ks < 32; ks += 16) {
            uint32_t ah[2][4], al[2][4], bh[2][4], bl[2][4];
#pragma unroll
            for (int ms = 0; ms < 2; ms++) {
                uint32_t off = (uint32_t)((wm + (ms << 4) + a_row) * GST + ks + a_kof) * 2;
                ldm_x4(ah[ms], uAh + off);
                ldm_x4(al[ms], uAl + off);
            }
#pragma unroll
            for (int g = 0; g < 2; g++) {
                uint32_t off = (uint32_t)((wn + (g << 4) + b_row) * GST + ks + b_kof) * 2;
                ldm_x4(bh[g], uBh + off);
                ldm_x4(bl[g], uBl + off);
            }
#pragma unroll
            for (int ms = 0; ms < 2; ms++)
#pragma unroll
                for (int g = 0; g < 2; g++)
#pragma unroll
                    for (int h = 0; h < 2; h++) {
                        float* dd = d[ms][(g << 1) + h];
                        mma_bf16(dd, ah[ms], &bh[g][h << 1]);
                        mma_bf16(dd, ah[ms], &bl[g][h << 1]);
                        mma_bf16(dd, al[ms], &bh[g][h << 1]);
                    }
        }
    }

    // ---- epilogue ----
    const int qr = lane >> 2;
    const int qc = (lane & 3) << 1;
#pragma unroll
    for (int ms = 0; ms < 2; ms++) {
#pragma unroll
        for (int half = 0; half < 2; half++) {
            int row = tm + wm + (ms << 4) + (half << 3) + qr;
            int b_ = 0, s_ = row;
            if (mode != 0) { b_ = row / len; s_ = row - b_ * len; }
#pragma unroll
            for (int ng = 0; ng < 4; ng++) {
                int col = tn + wn + (ng << 3) + qc;
                float v0 = (d[ms][ng][(half << 1) + 0] + bias[col]) * scale;
                float v1 = (d[ms][ng][(half << 1) + 1] + bias[col + 1]) * scale;
                if (mode == 0) {
                    *(float2*)&Cout[(size_t)row * EE + col] = make_float2(v0, v1);
                } else {
                    int h0 = col >> 6, d0 = col & 63;
                    __nv_bfloat16 h0b = __float2bfloat16(v0);
                    __nv_bfloat16 h1b = __float2bfloat16(v1);
                    __nv_bfloat16 l0b = __float2bfloat16(v0 - __bfloat162float(h0b));
                    __nv_bfloat16 l1b = __float2bfloat16(v1 - __bfloat162float(h1b));
                    if (mode == 3) {
                        size_t idx = (((size_t)b_ * HH + h0) * len + s_) * DD + d0;
                        *(uint32_t*)&Outh[idx] =
                            (uint32_t)__bfloat16_as_ushort(h0b) | ((uint32_t)__bfloat16_as_ushort(h1b) << 16);
                        *(uint32_t*)&Outl[idx] =
                            (uint32_t)__bfloat16_as_ushort(l0b) | ((uint32_t)__bfloat16_as_ushort(l1b) << 16);
                    } else {   // mode 4
                        size_t idx = (((size_t)b_ * HH + h0) * DD + d0) * (size_t)len + s_;
                        Outh[idx] = h0b; Outh[idx + len] = h1b;
                        Outl[idx] = l0b; Outl[idx + len] = l1b;
                    }
                }
            }
        }
    }
}

// ============================================================================
// HMMA flash attention: CTA = 128 s-rows of one (b,h). 8 warps, warp = m16.
// T streamed in 64-chunks. QK^T and PV both via bf16 2-term split HMMA.
// Q pre-scaled by 1/8 in projection. Raw scores spilled fp32 to praw.
// smem: Q hi/lo [128][72], K hi/lo [64][72] (t-major), V hi/lo [64][72] (d-major)
// ============================================================================
#define AST 72
#define ATT_SMEM_BYTES ((128*2 + 64*4) * AST * 2)   // 73728 B

__global__ __launch_bounds__(256) void attn_mma_kernel(
    const __nv_bfloat16* __restrict__ qh, const __nv_bfloat16* __restrict__ ql,
    const __nv_bfloat16* __restrict__ kh, const __nv_bfloat16* __restrict__ kl,
    const __nv_bfloat16* __restrict__ vh, const __nv_bfloat16* __restrict__ vl,
    float* __restrict__ ao, float* __restrict__ praw, float2* __restrict__ stat)
{
    extern __shared__ __align__(16) __nv_bfloat16 smb[];
    __nv_bfloat16* sQh = smb;
    __nv_bfloat16* sQl = sQh + 128 * AST;
    __nv_bfloat16* sKh = sQl + 128 * AST;
    __nv_bfloat16* sKl = sKh + 64 * AST;
    __nv_bfloat16* sVh = sKl + 64 * AST;
    __nv_bfloat16* sVl = sVh + 64 * AST;

    const int tid  = threadIdx.x;
    const int wid  = tid >> 5;
    const int lane = tid & 31;

    const int bh = blockIdx.x >> 4;              // SS/128 = 16 tiles/head
    const int st = (blockIdx.x & 15) << 7;
    const int b_ = bh >> 4;
    const int h_ = bh & 15;

    const uint32_t uQh = smem_to_u32(sQh), uQl = smem_to_u32(sQl);
    const uint32_t uKh = smem_to_u32(sKh), uKl = smem_to_u32(sKl);
    const uint32_t uVh = smem_to_u32(sVh), uVl = smem_to_u32(sVl);

    // ---- stage Q [128 s][64 d] hi/lo ----
    {
        const __nv_bfloat16* qhb = qh + ((size_t)bh * SS + st) * DD;
        const __nv_bfloat16* qlb = ql + ((size_t)bh * SS + st) * DD;
#pragma unroll
        for (int i = 0; i < 4; i++) {
            int idx = tid + (i << 8);
            int r = idx >> 3, d8 = (idx & 7) << 3;
            *(uint4*)&sQh[r * AST + d8] = *(const uint4*)(qhb + (size_t)r * DD + d8);
            *(uint4*)&sQl[r * AST + d8] = *(const uint4*)(qlb + (size_t)r * DD + d8);
        }
    }
    __syncthreads();

    // ---- resident Q fragments: warp rows 16*wid .. +15 ----
    const int wrow = wid << 4;
    const int a_row = lane & 15;
    const int a_kof = (lane >> 4) << 3;
    const int b_row = (lane & 7) + ((lane & 16) ? 8 : 0);
    const int b_kof = (lane & 8) ? 8 : 0;

    uint32_t qfh[4][4], qfl[4][4];
#pragma unroll
    for (int kk = 0; kk < 4; kk++) {
        uint32_t off = (uint32_t)((wrow + a_row) * AST + (kk << 4) + a_kof) * 2;
        ldm_x4(qfh[kk], uQh + off);
        ldm_x4(qfl[kk], uQl + off);
    }

    float oacc[8][4];
    float mrun[2] = {-1e30f, -1e30f}, zrun[2] = {0.f, 0.f};
#pragma unroll
    for (int j = 0; j < 8; j++)
#pragma unroll
        for (int e = 0; e < 4; e++) oacc[j][e] = 0.f;

    const __nv_bfloat16* khb = kh + (size_t)bh * TT * DD;
    const __nv_bfloat16* klb = kl + (size_t)bh * TT * DD;
    const __nv_bfloat16* vhb = vh + (size_t)bh * DD * TT;
    const __nv_bfloat16* vlb = vl + (size_t)bh * DD * TT;

    for (int c = 0; c < TT / 64; c++) {
        const int t0 = c << 6;
        __syncthreads();   // prev chunk's ldmatrix reads done
#pragma unroll
        for (int i = 0; i < 2; i++) {
            int idx = tid + (i << 8);
            int r = idx >> 3, c8 = (idx & 7) << 3;
            *(uint4*)&sKh[r * AST + c8] = *(const uint4*)(khb + (size_t)(t0 + r) * DD + c8);
            *(uint4*)&sKl[r * AST + c8] = *(const uint4*)(klb + (size_t)(t0 + r) * DD + c8);
            *(uint4*)&sVh[r * AST + c8] = *(const uint4*)(vhb + (size_t)r * TT + t0 + c8);
            *(uint4*)&sVl[r * AST + c8] = *(const uint4*)(vlb + (size_t)r * TT + t0 + c8);
        }
        __syncthreads();

        // ---- S = Q K^T (pre-scaled) : 8 n8-tiles x 4 k16 x 3 terms ----
        float sacc[8][4];
#pragma unroll
        for (int j = 0; j < 8; j++)
#pragma unroll
            for (int e = 0; e < 4; e++) sacc[j][e] = 0.f;

#pragma unroll
        for (int kk = 0; kk < 4; kk++) {
#pragma unroll
            for (int j2 = 0; j2 < 4; j2++) {
                uint32_t kbh[4], kbl[4];
                uint32_t off = (uint32_t)(((j2 << 4) + b_row) * AST + (kk << 4) + b_kof) * 2;
                ldm_x4(kbh, uKh + off);
                ldm_x4(kbl, uKl + off);
#pragma unroll
                for (int h = 0; h < 2; h++) {
                    float* dd = sacc[(j2 << 1) + h];
                    mma_bf16(dd, qfh[kk], &kbh[h << 1]);
                    mma_bf16(dd, qfh[kk], &kbl[h << 1]);
                    mma_bf16(dd, qfl[kk], &kbh[h << 1]);
                }
            }
        }

        // ---- spill raw scores (coalesced 256B per row from each quad group) ----
        {
            size_t base = ((size_t)bh * SS + st + wrow + (lane >> 2)) * TT + t0 + ((lane & 3) << 1);
#pragma unroll
            for (int j = 0; j < 8; j++) {
                *(float2*)&praw[base + (j << 3)]            = make_float2(sacc[j][0], sacc[j][1]);
                *(float2*)&praw[base + (size_t)8 * TT + (j << 3)] = make_float2(sacc[j][2], sacc[j][3]);
            }
        }

        // ---- online softmax (two rows per thread: r = lane>>2, r+8) ----
        float corr[2];
#pragma unroll
        for (int e = 0; e < 2; e++) {
            float m = -1e30f;
#pragma unroll
            for (int j = 0; j < 8; j++)
                m = fmaxf(m, fmaxf(sacc[j][(e << 1)], sacc[j][(e << 1) + 1]));
            m = fmaxf(m, __shfl_xor_sync(0xffffffffu, m, 1));
            m = fmaxf(m, __shfl_xor_sync(0xffffffffu, m, 2));
            float mn = fmaxf(mrun[e], m);
            corr[e] = __expf(mrun[e] - mn);
            mrun[e] = mn;
            float z = 0.f;
#pragma unroll
            for (int j = 0; j < 8; j++) {
                float p0 = __expf(sacc[j][(e << 1)] - mn);
                float p1 = __expf(sacc[j][(e << 1) + 1] - mn);
                sacc[j][(e << 1)] = p0;
                sacc[j][(e << 1) + 1] = p1;
                z += p0 + p1;
            }
            z += __shfl_xor_sync(0xffffffffu, z, 1);
            z += __shfl_xor_sync(0xffffffffu, z, 2);
            zrun[e] = zrun[e] * corr[e] + z;
#pragma unroll
            for (int j = 0; j < 8; j++) {
                oacc[j][(e << 1)]     *= corr[e];
                oacc[j][(e << 1) + 1] *= corr[e];
            }
        }

        // ---- O += P V : P split to hi/lo in registers ----
#pragma unroll
        for (int kk = 0; kk < 4; kk++) {
            uint32_t ph[4], pl[4];
#pragma unroll
            for (int q = 0; q < 4; q++) {
                int jt = (kk << 1) + (q >> 1);       // tile 2kk or 2kk+1
                int e0 = (q & 1) << 1;               // 0 or 2 (row half)
                float p0 = sacc[jt][e0], p1 = sacc[jt][e0 + 1];
                __nv_bfloat16 h0 = __float2bfloat16(p0), h1 = __float2bfloat16(p1);
                // A-frag order: a0=(r,k0k1) a1=(r+8,k0k1) a2=(r,k8k9) a3=(r+8,k8k9)
                int ai = ((q >> 1) << 1) + (q & 1);  // q0->a0, q1->a1, q2->a2, q3->a3
                ph[ai] = (uint32_t)__bfloat16_as_ushort(h0) | ((uint32_t)__bfloat16_as_ushort(h1) << 16);
                pl[ai] = bf16x2_hi(p0 - __bfloat162float(h0), p1 - __bfloat162float(h1));
            }
#pragma unroll
            for (int j2 = 0; j2 < 4; j2++) {
                uint32_t vbh[4], vbl[4];
                uint32_t off = (uint32_t)(((j2 << 4) + b_row) * AST + (kk << 4) + b_kof) * 2;
                ldm_x4(vbh, uVh + off);
                ldm_x4(vbl, uVl + off);
#pragma unroll
                for (int h = 0; h < 2; h++) {
                    float* dd = oacc[(j2 << 1) + h];
                    mma_bf16(dd, ph, &vbh[h << 1]);
                    mma_bf16(dd, ph, &vbl[h << 1]);
                    mma_bf16(dd, pl, &vbh[h << 1]);
                }
            }
        }
    }

    // ---- epilogue: normalize, write ao + stats ----
    float inv0 = 1.0f / zrun[0], inv1 = 1.0f / zrun[1];
    int row0 = st + wrow + (lane >> 2);
    float* ao0 = ao + ((size_t)b_ * SS + row0) * EE + h_ * DD + ((lane & 3) << 1);
    float* ao1 = ao0 + (size_t)8 * EE;
#pragma unroll
    for (int j = 0; j < 8; j++) {
        *(float2*)(ao0 + (j << 3)) = make_float2(oacc[j][0] * inv0, oacc[j][1] * inv0);
        *(float2*)(ao1 + (j << 3)) = make_float2(oacc[j][2] * inv1, oacc[j][3] * inv1);
    }
    if ((lane & 3) == 0) {
        stat[(size_t)bh * SS + row0]     = make_float2(mrun[0], inv0 * (1.0f / (float)HH));
        stat[(size_t)bh * SS + row0 + 8] = make_float2(mrun[1], inv1 * (1.0f / (float)HH));
    }
}

// ============================================================================
// avg_attn reconstruction (unchanged)
// ============================================================================
__global__ __launch_bounds__(256) void avg_kernel(
    const float* __restrict__ praw, const float2* __restrict__ stat,
    float* __restrict__ avg)
{
    size_t gi = (size_t)blockIdx.x * 256 + threadIdx.x;
    int    t4 = (int)(gi & (TT / 4 - 1)) << 2;
    size_t bs = gi >> 8;
    int b_ = (int)(bs >> 11);
    int s_ = (int)(bs & (SS - 1));

    float a0 = 0.f, a1 = 0.f, a2 = 0.f, a3 = 0.f;
#pragma unroll
    for (int h = 0; h < HH; h++) {
        size_t row = ((size_t)(b_ * HH + h) * SS + s_);
        float2 mz = stat[row];
        float4 r  = *(const float4*)&praw[row * TT + t4];
        a0 += __expf(r.x - mz.x) * mz.y;
        a1 += __expf(r.y - mz.x) * mz.y;
        a2 += __expf(r.z - mz.x) * mz.y;
        a3 += __expf(r.w - mz.x) * mz.y;
    }
    *(float4*)&avg[bs * TT + t4] = make_float4(a0, a1, a2, a3);
}

// ============================================================================
// Launch
// ============================================================================
extern "C" void kernel_launch(void* const* d_in, const int* in_sizes, int n_in,
                              void* d_out, int out_size)
{
    const float* x   = (const float*)d_in[0];
    const float* enc = (const float*)d_in[1];
    const float* Wq  = (const float*)d_in[2];
    const float* bq  = (const float*)d_in[3];
    const float* Wk  = (const float*)d_in[4];
    const float* bk  = (const float*)d_in[5];
    const float* Wv  = (const float*)d_in[6];
    const float* bv  = (const float*)d_in[7];
    const float* Wo  = (const float*)d_in[8];
    const float* bo  = (const float*)d_in[9];

    float* out = (float*)d_out;                       // [B,S,E]
    float* avg = out + (size_t)BB * SS * EE;          // [B,S,T]

    float *aop, *prp;
    float2* stp;
    cudaGetSymbolAddress((void**)&aop, g_ao);
    cudaGetSymbolAddress((void**)&prp, g_praw);
    cudaGetSymbolAddress((void**)&stp, g_stat);

    __nv_bfloat16 *xh, *xl, *eh, *el, *aoh, *aol;
    __nv_bfloat16 *wqh, *wql, *wkh, *wkl, *wvh, *wvl, *woh, *wol;
    __nv_bfloat16 *qbh, *qbl, *kbh, *kbl, *vbh, *vbl;
    cudaGetSymbolAddress((void**)&xh,  g_xh);  cudaGetSymbolAddress((void**)&xl,  g_xl);
    cudaGetSymbolAddress((void**)&eh,  g_eh);  cudaGetSymbolAddress((void**)&el,  g_el);
    cudaGetSymbolAddress((void**)&aoh, g_aoh); cudaGetSymbolAddress((void**)&aol, g_aol);
    cudaGetSymbolAddress((void**)&wqh, g_wqh); cudaGetSymbolAddress((void**)&wql, g_wql);
    cudaGetSymbolAddress((void**)&wkh, g_wkh); cudaGetSymbolAddress((void**)&wkl, g_wkl);
    cudaGetSymbolAddress((void**)&wvh, g_wvh); cudaGetSymbolAddress((void**)&wvl, g_wvl);
    cudaGetSymbolAddress((void**)&woh, g_woh); cudaGetSymbolAddress((void**)&wol, g_wol);
    cudaGetSymbolAddress((void**)&qbh, g_qbh); cudaGetSymbolAddress((void**)&qbl, g_qbl);
    cudaGetSymbolAddress((void**)&kbh, g_kbh); cudaGetSymbolAddress((void**)&kbl, g_kbl);
    cudaGetSymbolAddress((void**)&vbh, g_vbh); cudaGetSymbolAddress((void**)&vbl, g_vbl);

    cudaFuncSetAttribute(attn_mma_kernel,
                         cudaFuncAttributeMaxDynamicSharedMemorySize, ATT_SMEM_BYTES);

    // ---- split inputs to bf16 hi/lo ----
    const int n4x = BB * SS * EE / 4;
    const int n4e = BB * TT * CC / 4;
    split_kernel<<<n4x / 256, 256>>>((const float4*)x,   (uint2*)xh, (uint2*)xl, n4x);
    split_kernel<<<n4e / 256, 256>>>((const float4*)enc, (uint2*)eh, (uint2*)el, n4e);
    wsplit_kernel<<<dim3(EE / 32, EE / 32), dim3(32, 8)>>>(Wq, wqh, wql, EE, EE);
    wsplit_kernel<<<dim3(EE / 32, CC / 32), dim3(32, 8)>>>(Wk, wkh, wkl, CC, EE);
    wsplit_kernel<<<dim3(EE / 32, CC / 32), dim3(32, 8)>>>(Wv, wvh, wvl, CC, EE);
    wsplit_kernel<<<dim3(EE / 32, EE / 32), dim3(32, 8)>>>(Wo, woh, wol, EE, EE);

    // ---- projections: write bf16 hi/lo attention operands directly ----
    gemm_mma_kernel<<<dim3(EE / 128, BB * SS / 128), 512>>>(
        xh, xl, wqh, wql, bq, nullptr, qbh, qbl, 0.125f, EE, SS, 3);   // Q, pre-scaled 1/sqrt(64)
    gemm_mma_kernel<<<dim3(EE / 128, BB * TT / 128), 512>>>(
        eh, el, wkh, wkl, bk, nullptr, kbh, kbl, 1.0f, CC, TT, 3);     // K [B,H,T,D]
    gemm_mma_kernel<<<dim3(EE / 128, BB * TT / 128), 512>>>(
        eh, el, wvh, wvl, bv, nullptr, vbh, vbl, 1.0f, CC, TT, 4);     // V [B,H,D,T]

    // ---- attention (HMMA flash) ----
    attn_mma_kernel<<<BB * HH * (SS / 128), 256, ATT_SMEM_BYTES>>>(
        qbh, qbl, kbh, kbl, vbh, vbl, aop, prp, stp);

    // ---- output projection ----
    split_kernel<<<n4x / 256, 256>>>((const float4*)aop, (uint2*)aoh, (uint2*)aol, n4x);
    gemm_mma_kernel<<<dim3(EE / 128, BB * SS / 128), 512>>>(
        aoh, aol, woh, wol, bo, out, nullptr, nullptr, 1.0f, EE, 0, 0);

    // ---- avg_attn ----
    avg_kernel<<<(unsigned)((size_t)BB * SS * (TT / 4) / 256), 256>>>(prp, stp, avg);
}